// round 1
// baseline (speedup 1.0000x reference)
#include <cuda_runtime.h>
#include <cstdint>
#include <cstddef>

// EncoderRNN: y = GRU(Linear(x)), B=256, T=1024, IN=64, H=256.
// Strategy: fold Linear into GRU input gates (W_comb = W_ih @ W_lin), then run the
// sequential recurrence in ONE persistent kernel. Batch elements are independent,
// so the only sharing is the weights: an 8-CTA cluster keeps the full fused weight
// matrix [W_hh | W_comb] (768 x 320 fp32) in shared memory, 96 rows per CTA.
// Each cluster owns 16 batch elements; each CTA computes 32 h-units for all 16,
// then broadcasts its h_new slice to all 8 peer CTAs via DSMEM stores, with one
// cluster barrier per timestep and double-buffered h state.

#define BATCH   256
#define TT      1024
#define INDIM   64
#define HH      256
#define CL      8            // cluster size (CTAs)
#define NB      16           // batch elements per cluster
#define NU      32           // h-units per CTA
#define NROW    (3*NU)       // gate rows per CTA (96)
#define THREADS 512          // 32 units x 16 batch
#define KAUG    (HH + INDIM) // 320 fused K
#define WSTR    324          // padded row stride (words); 324 % 32 == 4 -> conflict-free w loads

__device__ __forceinline__ uint32_t smem_u32(const void* p) {
    uint32_t a;
    asm("{ .reg .u64 t; cvta.to.shared.u64 t, %1; cvt.u32.u64 %0, t; }"
        : "=r"(a) : "l"(p));
    return a;
}

__device__ __forceinline__ void dsmem_st_f32(uint32_t laddr, uint32_t rank, float v) {
    uint32_t ra;
    asm volatile("mapa.shared::cluster.u32 %0, %1, %2;" : "=r"(ra) : "r"(laddr), "r"(rank));
    asm volatile("st.shared::cluster.f32 [%0], %1;" :: "r"(ra), "f"(v) : "memory");
}

__device__ __forceinline__ void cluster_sync() {
    asm volatile("barrier.cluster.arrive.aligned;" ::: "memory");
    asm volatile("barrier.cluster.wait.aligned;" ::: "memory");
}

extern __shared__ float smem[];

__global__ void __cluster_dims__(CL, 1, 1) __launch_bounds__(THREADS, 1)
gru_fused_kernel(const float* __restrict__ inp,     // [B,T,IN]
                 const float* __restrict__ hidden,  // [1,B,H]
                 const float* __restrict__ W_lin,   // [H,IN]
                 const float* __restrict__ b_lin,   // [H]
                 const float* __restrict__ W_ih,    // [3H,H]
                 const float* __restrict__ b_ih,    // [3H]
                 const float* __restrict__ W_hh,    // [3H,H]
                 const float* __restrict__ b_hh,    // [3H]
                 float* __restrict__ out,           // [B,T,H] (+ optional [B,H] tail)
                 int write_hlast)
{
    // Shared layout (floats):
    //   waug  [NROW][WSTR] : fused rows [W_hh row | W_comb row | pad]
    //   haug  [2][NB][WSTR]: double-buffered [h (256) | x_t (64) | pad]
    //   bias_i[NROW], bias_h[NROW]
    float* waug   = smem;
    float* haug   = waug + NROW * WSTR;
    float* bias_i = haug + 2 * NB * WSTR;
    float* bias_h = bias_i + NROW;

    const int tid = threadIdx.x;
    uint32_t crank;
    asm("mov.u32 %0, %%cluster_ctarank;" : "=r"(crank));
    const int c  = blockIdx.x / CL;     // cluster id
    const int b0 = c * NB;              // first batch element of this cluster

    // ---------------- Prologue ----------------
    // 1) W_hh rows for this CTA's 96 gate rows
    for (int f = tid; f < NROW * HH; f += THREADS) {
        int lr = f >> 8, k = f & 255;           // local row, k
        int g = lr >> 5, ul = lr & 31;
        int R = (g << 8) + (int)crank * NU + ul;
        waug[lr * WSTR + k] = W_hh[R * HH + k];
    }
    // 2) W_comb = W_ih @ W_lin (only this CTA's 96 rows), into waug[..][256:320]
    {
        int i = tid & 63, lr0 = tid >> 6;       // i in [0,64), lr0 in [0,8)
        for (int jj = 0; jj < 12; jj++) {
            int lr = lr0 + 8 * jj;              // [0,96)
            int g = lr >> 5, ul = lr & 31;
            int R = (g << 8) + (int)crank * NU + ul;
            const float4* wih = (const float4*)(W_ih + (size_t)R * HH);
            float s = 0.f;
            #pragma unroll 8
            for (int m4 = 0; m4 < HH / 4; m4++) {
                float4 w = wih[m4];
                int m = m4 << 2;
                s = fmaf(w.x, W_lin[(m + 0) * INDIM + i], s);
                s = fmaf(w.y, W_lin[(m + 1) * INDIM + i], s);
                s = fmaf(w.z, W_lin[(m + 2) * INDIM + i], s);
                s = fmaf(w.w, W_lin[(m + 3) * INDIM + i], s);
            }
            waug[lr * WSTR + HH + i] = s;
        }
    }
    // 3) biases: bias_i = b_ih + W_ih @ b_lin ; bias_h = b_hh
    if (tid < NROW) {
        int lr = tid, g = lr >> 5, ul = lr & 31;
        int R = (g << 8) + (int)crank * NU + ul;
        float s = b_ih[R];
        for (int m = 0; m < HH; m++) s = fmaf(W_ih[R * HH + m], b_lin[m], s);
        bias_i[lr] = s;
        bias_h[lr] = b_hh[R];
    }
    // 4) h0 into buffer 0
    for (int f = tid; f < NB * HH; f += THREADS) {
        int b = f >> 8, k = f & 255;
        haug[b * WSTR + k] = hidden[(b0 + b) * HH + k];
    }
    // 5) x(0) into buffer 0; prefetch x(1) into registers
    float2 xpre;
    const int xb = tid >> 5;                 // [0,16): batch for x staging
    const int xi = (tid << 1) & 63;          // [0,64): even
    {
        const float* xrow = inp + ((size_t)(b0 + xb) * TT) * INDIM + xi;
        float2 v = *(const float2*)xrow;
        haug[xb * WSTR + HH + xi]     = v.x;
        haug[xb * WSTR + HH + xi + 1] = v.y;
        xpre = *(const float2*)(xrow + INDIM);   // x at t=1
    }
    __syncthreads();
    cluster_sync();

    // ---------------- Main recurrence ----------------
    const int u = tid >> 4;                      // unit within CTA [0,32)
    const int q = tid & 15;                      // batch within cluster [0,16)
    const int jglob = (int)crank * NU + u;       // global h index [0,256)
    const int bg = b0 + q;                       // global batch

    const float bi_r = bias_i[u], bi_z = bias_i[NU + u], bi_n = bias_i[2 * NU + u];
    const float bh_r = bias_h[u], bh_z = bias_h[NU + u], bh_n = bias_h[2 * NU + u];

    const float4* wr4 = (const float4*)(waug + (0 * NU + u) * WSTR);
    const float4* wz4 = (const float4*)(waug + (1 * NU + u) * WSTR);
    const float4* wn4 = (const float4*)(waug + (2 * NU + u) * WSTR);
    const uint32_t haug_sm = smem_u32(haug);

    for (int t = 0; t < TT; t++) {
        const int p = t & 1;
        const float* hv = haug + (p * NB + q) * WSTR;
        const float4* h4p = (const float4*)hv;

        float ar = 0.f, az = 0.f, anh = 0.f, anx = 0.f;
        // h-part: k in [0,256)
        #pragma unroll 8
        for (int kk = 0; kk < HH / 4; kk++) {
            float4 h4 = h4p[kk];
            float4 a4 = wr4[kk];
            ar = fmaf(a4.x, h4.x, ar); ar = fmaf(a4.y, h4.y, ar);
            ar = fmaf(a4.z, h4.z, ar); ar = fmaf(a4.w, h4.w, ar);
            float4 b4 = wz4[kk];
            az = fmaf(b4.x, h4.x, az); az = fmaf(b4.y, h4.y, az);
            az = fmaf(b4.z, h4.z, az); az = fmaf(b4.w, h4.w, az);
            float4 c4 = wn4[kk];
            anh = fmaf(c4.x, h4.x, anh); anh = fmaf(c4.y, h4.y, anh);
            anh = fmaf(c4.z, h4.z, anh); anh = fmaf(c4.w, h4.w, anh);
        }
        // x-part: k in [256,320) -> n-gate input side kept separate (anx)
        #pragma unroll
        for (int kk = HH / 4; kk < KAUG / 4; kk++) {
            float4 h4 = h4p[kk];
            float4 a4 = wr4[kk];
            ar = fmaf(a4.x, h4.x, ar); ar = fmaf(a4.y, h4.y, ar);
            ar = fmaf(a4.z, h4.z, ar); ar = fmaf(a4.w, h4.w, ar);
            float4 b4 = wz4[kk];
            az = fmaf(b4.x, h4.x, az); az = fmaf(b4.y, h4.y, az);
            az = fmaf(b4.z, h4.z, az); az = fmaf(b4.w, h4.w, az);
            float4 c4 = wn4[kk];
            anx = fmaf(c4.x, h4.x, anx); anx = fmaf(c4.y, h4.y, anx);
            anx = fmaf(c4.z, h4.z, anx); anx = fmaf(c4.w, h4.w, anx);
        }

        // gates
        float rg = 1.f / (1.f + expf(-(ar + bi_r + bh_r)));
        float zg = 1.f / (1.f + expf(-(az + bi_z + bh_z)));
        float ng = tanhf(anx + bi_n + rg * (anh + bh_n));
        float hold = hv[jglob];
        float hn = (1.f - zg) * ng + zg * hold;

        // outputs
        out[((size_t)bg * TT + t) * HH + jglob] = hn;
        if (write_hlast && t == TT - 1)
            out[(size_t)BATCH * TT * HH + (size_t)bg * HH + jglob] = hn;

        // stage x(t+1) into next buffer (x slots disjoint from peers' h writes)
        if (t < TT - 1) {
            float* hx = haug + ((1 - p) * NB + xb) * WSTR + HH + xi;
            hx[0] = xpre.x; hx[1] = xpre.y;
            if (t < TT - 2)
                xpre = *(const float2*)(inp + ((size_t)(b0 + xb) * TT + (t + 2)) * INDIM + xi);
        }

        // broadcast h_new slice to all cluster CTAs' next buffer
        uint32_t la = haug_sm + (uint32_t)((((1 - p) * NB + q) * WSTR + jglob) * 4);
        #pragma unroll
        for (int rr = 0; rr < CL; rr++) dsmem_st_f32(la, (uint32_t)rr, hn);

        cluster_sync();  // release DSMEM writes; gates next step's reads
    }
}

extern "C" void kernel_launch(void* const* d_in, const int* in_sizes, int n_in,
                              void* d_out, int out_size) {
    (void)in_sizes; (void)n_in;
    const float* inp    = (const float*)d_in[0];
    const float* hidden = (const float*)d_in[1];
    const float* W_lin  = (const float*)d_in[2];
    const float* b_lin  = (const float*)d_in[3];
    const float* W_ih   = (const float*)d_in[4];
    const float* b_ih   = (const float*)d_in[5];
    const float* W_hh   = (const float*)d_in[6];
    const float* b_hh   = (const float*)d_in[7];

    const int smem_bytes = (NROW * WSTR + 2 * NB * WSTR + 2 * NROW) * (int)sizeof(float);
    cudaFuncSetAttribute(gru_fused_kernel,
                         cudaFuncAttributeMaxDynamicSharedMemorySize, smem_bytes);

    const int write_hlast = (out_size > BATCH * TT * HH) ? 1 : 0;
    const int grid = (BATCH / NB) * CL;  // 16 clusters * 8 CTAs = 128
    gru_fused_kernel<<<grid, THREADS, smem_bytes>>>(
        inp, hidden, W_lin, b_lin, W_ih, b_ih, W_hh, b_hh,
        (float*)d_out, write_hlast);
}

// round 2
// speedup vs baseline: 1.4679x; 1.4679x over previous
#include <cuda_runtime.h>
#include <cstdint>
#include <cstddef>

// EncoderRNN: y = GRU(Linear(x)), B=256, T=1024, IN=64, H=256.
// 8-CTA cluster holds fused weights [W_hh | W_ih@W_lin] (768x320 fp32) in smem,
// 96 rows/CTA. 16 clusters x 16 batch = 256. Per step each CTA computes 32 h-units
// for 16 batch elements using packed f32x2 FMA (2 batch/thread, 256 threads),
// then distributes its h_new slice to all 8 peers with st.async + mbarrier tx
// (no cluster.sync in the loop), double-buffered h state.

#define BATCH   256
#define TT      1024
#define INDIM   64
#define HH      256
#define CL      8
#define NB      16
#define NU      32
#define NROW    (3*NU)       // 96
#define THREADS 256          // 32 u x 8 q (each thread does q and q+8)
#define KAUG    (HH + INDIM) // 320
#define WSTR    324          // padded stride (words); 324 % 32 == 4
#define TXB     16384        // bytes arriving per CTA per step (16*256*4)

typedef unsigned long long ull;

__device__ __forceinline__ uint32_t smem_u32(const void* p) {
    uint32_t a;
    asm("{ .reg .u64 t; cvta.to.shared.u64 t, %1; cvt.u32.u64 %0, t; }"
        : "=r"(a) : "l"(p));
    return a;
}
__device__ __forceinline__ void ffma2(ull& d, ull a, ull b) {
    asm("fma.rn.f32x2 %0, %1, %2, %0;" : "+l"(d) : "l"(a), "l"(b));
}
__device__ __forceinline__ float hsum2(ull v) {
    float x, y;
    asm("mov.b64 {%0, %1}, %2;" : "=f"(x), "=f"(y) : "l"(v));
    return x + y;
}
__device__ __forceinline__ void st_async_f32(uint32_t laddr, uint32_t lmbar,
                                             uint32_t rank, float v) {
    uint32_t ra, rb;
    asm volatile("mapa.shared::cluster.u32 %0, %1, %2;" : "=r"(ra) : "r"(laddr), "r"(rank));
    asm volatile("mapa.shared::cluster.u32 %0, %1, %2;" : "=r"(rb) : "r"(lmbar), "r"(rank));
    asm volatile("st.async.shared::cluster.mbarrier::complete_tx::bytes.b32 [%0], %1, [%2];"
                 :: "r"(ra), "f"(v), "r"(rb) : "memory");
}
__device__ __forceinline__ void mbar_init(uint32_t a, uint32_t cnt) {
    asm volatile("mbarrier.init.shared.b64 [%0], %1;" :: "r"(a), "r"(cnt) : "memory");
}
__device__ __forceinline__ void mbar_expect_tx(uint32_t a, uint32_t tx) {
    asm volatile("mbarrier.arrive.expect_tx.shared.b64 _, [%0], %1;" :: "r"(a), "r"(tx) : "memory");
}
__device__ __forceinline__ void mbar_wait(uint32_t a, uint32_t parity) {
    asm volatile("{\n\t.reg .pred P;\n"
                 "W%=:\n\t"
                 "mbarrier.try_wait.parity.acquire.cta.shared::cta.b64 P, [%0], %1, 0x989680;\n\t"
                 "@!P bra W%=;\n\t}"
                 :: "r"(a), "r"(parity) : "memory");
}
__device__ __forceinline__ void cluster_sync() {
    asm volatile("barrier.cluster.arrive.aligned;" ::: "memory");
    asm volatile("barrier.cluster.wait.aligned;" ::: "memory");
}
__device__ __forceinline__ float sigm(float x) {
    return __fdividef(1.f, 1.f + __expf(-x));
}
__device__ __forceinline__ float tanh_fast(float x) {
    float ax = fabsf(x);
    float e  = __expf(2.f * ax);                 // +inf ok
    float r  = 1.f - __fdividef(2.f, e + 1.f);   // -> 1 as e -> inf
    return copysignf(r, x);
}

extern __shared__ float smem[];

__global__ void __cluster_dims__(CL, 1, 1) __launch_bounds__(THREADS, 1)
gru_fused_kernel(const float* __restrict__ inp,     // [B,T,IN]
                 const float* __restrict__ hidden,  // [1,B,H]
                 const float* __restrict__ W_lin,   // [H,IN]
                 const float* __restrict__ b_lin,   // [H]
                 const float* __restrict__ W_ih,    // [3H,H]
                 const float* __restrict__ b_ih,    // [3H]
                 const float* __restrict__ W_hh,    // [3H,H]
                 const float* __restrict__ b_hh,    // [3H]
                 float* __restrict__ out,
                 int write_hlast)
{
    // smem layout (floats): waug[96][324] | haug[2][16][324] | bias_i[96] | bias_h[96] | mbar[2] (u64)
    float* waug   = smem;
    float* haug   = waug + NROW * WSTR;
    float* bias_i = haug + 2 * NB * WSTR;
    float* bias_h = bias_i + NROW;
    float* mbarf  = bias_h + NROW;              // 16 bytes, 8-aligned

    const int tid = threadIdx.x;
    uint32_t crank;
    asm("mov.u32 %0, %%cluster_ctarank;" : "=r"(crank));
    const int c  = blockIdx.x / CL;
    const int b0 = c * NB;

    const uint32_t mb0 = smem_u32(mbarf);
    const uint32_t mb1 = mb0 + 8;

    // ---------------- Prologue ----------------
    if (tid == 0) {
        mbar_init(mb0, 1); mbar_init(mb1, 1);
        mbar_expect_tx(mb0, TXB); mbar_expect_tx(mb1, TXB);
    }
    // W_hh rows for this CTA's 96 gate rows
    for (int f = tid; f < NROW * HH; f += THREADS) {
        int lr = f >> 8, k = f & 255;
        int g = lr >> 5, ul = lr & 31;
        int R = (g << 8) + (int)crank * NU + ul;
        waug[lr * WSTR + k] = W_hh[R * HH + k];
    }
    // W_comb = W_ih @ W_lin into waug[..][256:320]
    {
        int i = tid & 63, lr0 = tid >> 6;       // i in [0,64), lr0 in [0,4)
        for (int jj = 0; jj < 24; jj++) {
            int lr = lr0 + 4 * jj;
            int g = lr >> 5, ul = lr & 31;
            int R = (g << 8) + (int)crank * NU + ul;
            const float4* wih = (const float4*)(W_ih + (size_t)R * HH);
            float s = 0.f;
            #pragma unroll 8
            for (int m4 = 0; m4 < HH / 4; m4++) {
                float4 w = wih[m4];
                int m = m4 << 2;
                s = fmaf(w.x, W_lin[(m + 0) * INDIM + i], s);
                s = fmaf(w.y, W_lin[(m + 1) * INDIM + i], s);
                s = fmaf(w.z, W_lin[(m + 2) * INDIM + i], s);
                s = fmaf(w.w, W_lin[(m + 3) * INDIM + i], s);
            }
            waug[lr * WSTR + HH + i] = s;
        }
    }
    // biases
    if (tid < NROW) {
        int lr = tid, g = lr >> 5, ul = lr & 31;
        int R = (g << 8) + (int)crank * NU + ul;
        float s = b_ih[R];
        for (int m = 0; m < HH; m++) s = fmaf(W_ih[R * HH + m], b_lin[m], s);
        bias_i[lr] = s;
        bias_h[lr] = b_hh[R];
    }
    // h0 into buffer 0
    for (int f = tid; f < NB * HH; f += THREADS) {
        int b = f >> 8, k = f & 255;
        haug[b * WSTR + k] = hidden[(b0 + b) * HH + k];
    }
    // x(0) into buffer 0; prefetch x(1)
    float4 xpre;
    const int xb = tid >> 4;                 // [0,16)
    const int xi = (tid & 15) << 2;          // [0,64) step 4
    {
        const float* xrow = inp + ((size_t)(b0 + xb) * TT) * INDIM + xi;
        float4 v = *(const float4*)xrow;
        *(float4*)(haug + xb * WSTR + HH + xi) = v;
        xpre = *(const float4*)(xrow + INDIM);
    }
    __syncthreads();
    cluster_sync();   // peers' mbarriers initialized before any st.async

    // ---------------- Main recurrence ----------------
    const int u  = tid >> 3;                 // [0,32)
    const int qa = tid & 7;                  // [0,8)
    const int qb = qa + 8;
    const int jglob = (int)crank * NU + u;
    const int bga = b0 + qa, bgb = b0 + qb;

    const float bi_r = bias_i[u], bi_z = bias_i[NU + u], bi_n = bias_i[2 * NU + u];
    const float bh_r = bias_h[u], bh_z = bias_h[NU + u], bh_n = bias_h[2 * NU + u];

    const ulonglong2* wr2 = (const ulonglong2*)(waug + (0 * NU + u) * WSTR);
    const ulonglong2* wz2 = (const ulonglong2*)(waug + (1 * NU + u) * WSTR);
    const ulonglong2* wn2 = (const ulonglong2*)(waug + (2 * NU + u) * WSTR);
    const uint32_t haug_sm = smem_u32(haug);
    uint32_t mbs[2] = { mb0, mb1 };
    uint32_t ph[2]  = { 0, 0 };

    for (int t = 0; t < TT; t++) {
        const int p = t & 1;
        const float* hva = haug + (p * NB + qa) * WSTR;
        const float* hvb = haug + (p * NB + qb) * WSTR;
        const ulonglong2* h2a = (const ulonglong2*)hva;
        const ulonglong2* h2b = (const ulonglong2*)hvb;

        ull ra = 0, za = 0, nha = 0, nxa = 0;
        ull rb = 0, zb = 0, nhb = 0, nxb = 0;

        #pragma unroll 4
        for (int kk = 0; kk < 64; kk++) {       // k in [0,256): h part
            ulonglong2 wr = wr2[kk], wz = wz2[kk], wn = wn2[kk];
            ulonglong2 ha = h2a[kk], hb = h2b[kk];
            ffma2(ra, wr.x, ha.x);  ffma2(ra, wr.y, ha.y);
            ffma2(za, wz.x, ha.x);  ffma2(za, wz.y, ha.y);
            ffma2(nha, wn.x, ha.x); ffma2(nha, wn.y, ha.y);
            ffma2(rb, wr.x, hb.x);  ffma2(rb, wr.y, hb.y);
            ffma2(zb, wz.x, hb.x);  ffma2(zb, wz.y, hb.y);
            ffma2(nhb, wn.x, hb.x); ffma2(nhb, wn.y, hb.y);
        }
        #pragma unroll 4
        for (int kk = 64; kk < 80; kk++) {      // k in [256,320): x part (n-gate -> nx)
            ulonglong2 wr = wr2[kk], wz = wz2[kk], wn = wn2[kk];
            ulonglong2 ha = h2a[kk], hb = h2b[kk];
            ffma2(ra, wr.x, ha.x);  ffma2(ra, wr.y, ha.y);
            ffma2(za, wz.x, ha.x);  ffma2(za, wz.y, ha.y);
            ffma2(nxa, wn.x, ha.x); ffma2(nxa, wn.y, ha.y);
            ffma2(rb, wr.x, hb.x);  ffma2(rb, wr.y, hb.y);
            ffma2(zb, wz.x, hb.x);  ffma2(zb, wz.y, hb.y);
            ffma2(nxb, wn.x, hb.x); ffma2(nxb, wn.y, hb.y);
        }

        // gates
        float rg_a = sigm(hsum2(ra) + bi_r + bh_r);
        float zg_a = sigm(hsum2(za) + bi_z + bh_z);
        float ng_a = tanh_fast(hsum2(nxa) + bi_n + rg_a * (hsum2(nha) + bh_n));
        float hold_a = hva[jglob];
        float hn_a = (1.f - zg_a) * ng_a + zg_a * hold_a;

        float rg_b = sigm(hsum2(rb) + bi_r + bh_r);
        float zg_b = sigm(hsum2(zb) + bi_z + bh_z);
        float ng_b = tanh_fast(hsum2(nxb) + bi_n + rg_b * (hsum2(nhb) + bh_n));
        float hold_b = hvb[jglob];
        float hn_b = (1.f - zg_b) * ng_b + zg_b * hold_b;

        // outputs
        out[((size_t)bga * TT + t) * HH + jglob] = hn_a;
        out[((size_t)bgb * TT + t) * HH + jglob] = hn_b;
        if (write_hlast && t == TT - 1) {
            out[(size_t)BATCH * TT * HH + (size_t)bga * HH + jglob] = hn_a;
            out[(size_t)BATCH * TT * HH + (size_t)bgb * HH + jglob] = hn_b;
        }

        if (t < TT - 1) {
            // stage x(t+1) into next buffer (local region disjoint from peer h writes)
            *(float4*)(haug + ((1 - p) * NB + xb) * WSTR + HH + xi) = xpre;
            if (t < TT - 2)
                xpre = *(const float4*)(inp + ((size_t)(b0 + xb) * TT + (t + 2)) * INDIM + xi);

            // distribute h_new slice to all 8 CTAs' next buffer, tx-signaling their mbar
            const int bnext = 1 - p;
            uint32_t la_a = haug_sm + (uint32_t)(((bnext * NB + qa) * WSTR + jglob) * 4);
            uint32_t la_b = haug_sm + (uint32_t)(((bnext * NB + qb) * WSTR + jglob) * 4);
            uint32_t lm   = mbs[bnext];
            #pragma unroll
            for (int rr = 0; rr < CL; rr++) {
                st_async_f32(la_a, lm, (uint32_t)rr, hn_a);
                st_async_f32(la_b, lm, (uint32_t)rr, hn_b);
            }
            __syncthreads();              // orders local x STS before peers... (local readers)
            mbar_wait(mbs[bnext], ph[bnext]);
            ph[bnext] ^= 1;
            if (tid == 0) mbar_expect_tx(mbs[bnext], TXB);  // re-arm for t+2
        }
    }
    cluster_sync();   // no CTA exits while peers could still reference cluster smem
}

extern "C" void kernel_launch(void* const* d_in, const int* in_sizes, int n_in,
                              void* d_out, int out_size) {
    (void)in_sizes; (void)n_in;
    const float* inp    = (const float*)d_in[0];
    const float* hidden = (const float*)d_in[1];
    const float* W_lin  = (const float*)d_in[2];
    const float* b_lin  = (const float*)d_in[3];
    const float* W_ih   = (const float*)d_in[4];
    const float* b_ih   = (const float*)d_in[5];
    const float* W_hh   = (const float*)d_in[6];
    const float* b_hh   = (const float*)d_in[7];

    const int smem_bytes = (NROW * WSTR + 2 * NB * WSTR + 2 * NROW) * (int)sizeof(float) + 16;
    cudaFuncSetAttribute(gru_fused_kernel,
                         cudaFuncAttributeMaxDynamicSharedMemorySize, smem_bytes);

    const int write_hlast = (out_size > BATCH * TT * HH) ? 1 : 0;
    const int grid = (BATCH / NB) * CL;   // 128
    gru_fused_kernel<<<grid, THREADS, smem_bytes>>>(
        inp, hidden, W_lin, b_lin, W_ih, b_ih, W_hh, b_hh,
        (float*)d_out, write_hlast);
}

// round 3
// speedup vs baseline: 1.7134x; 1.1673x over previous
#include <cuda_runtime.h>
#include <cstdint>
#include <cstddef>

// EncoderRNN: y = GRU(Linear(x)), B=256, T=1024, IN=64, H=256.
// 8-CTA cluster holds fused weights [W_hh | W_ih@W_lin] (768x320 fp32) in smem.
// Per step each CTA computes its 32 h-units for 16 batch elems (f32x2 FMA,
// 2 batch/thread), stages them in smem, and bulk-copies one 2304B block to each
// peer via cp.async.bulk.shared::cluster (8 tx-updates per mbarrier per step).

#define BATCH   256
#define TT      1024
#define INDIM   64
#define HH      256
#define CL      8
#define NB      16
#define NU      32
#define NROW    (3*NU)        // 96
#define THREADS 256
#define WSTR    324           // weight row stride (floats); %32==4
#define CHSTR   36            // h-chunk row stride (floats); %32==4
#define CHUNK   (NB*CHSTR)    // 576 floats = 2304 B per (srcCTA) block
#define XSTR    68            // x row stride (floats); %32==4
#define TXB     (CL*CHUNK*4)  // 18432 B expected per buffer per step

typedef unsigned long long ull;

__device__ __forceinline__ uint32_t smem_u32(const void* p) {
    uint32_t a;
    asm("{ .reg .u64 t; cvta.to.shared.u64 t, %1; cvt.u32.u64 %0, t; }"
        : "=r"(a) : "l"(p));
    return a;
}
__device__ __forceinline__ void ffma2(ull& d, ull a, ull b) {
    asm("fma.rn.f32x2 %0, %1, %2, %0;" : "+l"(d) : "l"(a), "l"(b));
}
__device__ __forceinline__ float hsum2(ull v) {
    float x, y;
    asm("mov.b64 {%0, %1}, %2;" : "=f"(x), "=f"(y) : "l"(v));
    return x + y;
}
__device__ __forceinline__ void dsmem_bulk_cp(uint32_t dst_l, uint32_t src_l,
                                              uint32_t mbar_l, uint32_t rank,
                                              uint32_t bytes) {
    uint32_t rd, rm;
    asm volatile("mapa.shared::cluster.u32 %0, %1, %2;" : "=r"(rd) : "r"(dst_l),  "r"(rank));
    asm volatile("mapa.shared::cluster.u32 %0, %1, %2;" : "=r"(rm) : "r"(mbar_l), "r"(rank));
    asm volatile("cp.async.bulk.shared::cluster.shared::cta.mbarrier::complete_tx::bytes "
                 "[%0], [%1], %2, [%3];"
                 :: "r"(rd), "r"(src_l), "r"(bytes), "r"(rm) : "memory");
}
__device__ __forceinline__ void mbar_init(uint32_t a, uint32_t cnt) {
    asm volatile("mbarrier.init.shared.b64 [%0], %1;" :: "r"(a), "r"(cnt) : "memory");
}
__device__ __forceinline__ void mbar_expect_tx(uint32_t a, uint32_t tx) {
    asm volatile("mbarrier.arrive.expect_tx.shared.b64 _, [%0], %1;" :: "r"(a), "r"(tx) : "memory");
}
__device__ __forceinline__ void mbar_wait(uint32_t a, uint32_t parity) {
    asm volatile("{\n\t.reg .pred P;\n"
                 "W%=:\n\t"
                 "mbarrier.try_wait.parity.acquire.cta.shared::cta.b64 P, [%0], %1, 0x989680;\n\t"
                 "@!P bra W%=;\n\t}"
                 :: "r"(a), "r"(parity) : "memory");
}
__device__ __forceinline__ void fence_async_shared() {
    asm volatile("fence.proxy.async.shared::cta;" ::: "memory");
}
__device__ __forceinline__ void cluster_sync() {
    asm volatile("barrier.cluster.arrive.aligned;" ::: "memory");
    asm volatile("barrier.cluster.wait.aligned;" ::: "memory");
}
__device__ __forceinline__ float sigm(float x) {
    return __fdividef(1.f, 1.f + __expf(-x));
}
__device__ __forceinline__ float tanh_fast(float x) {
    float ax = fabsf(x);
    float e  = __expf(2.f * ax);
    float r  = 1.f - __fdividef(2.f, e + 1.f);
    return copysignf(r, x);
}

extern __shared__ float smem[];

// smem layout (float offsets):
//   waug   [96][324]        @ 0        (31104)
//   hbuf   [2][8][16][36]   @ 31104    (9216)   chunked h, double buffered
//   xbuf   [2][16][68]      @ 40320    (2176)
//   stage  [2][16][36]      @ 42496    (1152)
//   bias_i [96]             @ 43648
//   bias_h [96]             @ 43744
//   mbar   [2] u64          @ 43840
#define OFF_W     0
#define OFF_H     31104
#define OFF_X     40320
#define OFF_ST    42496
#define OFF_BI    43648
#define OFF_BH    43744
#define OFF_MB    43840
#define SMEM_FL   (43840 + 4)

__global__ void __cluster_dims__(CL, 1, 1) __launch_bounds__(THREADS, 1)
gru_fused_kernel(const float* __restrict__ inp,
                 const float* __restrict__ hidden,
                 const float* __restrict__ W_lin,
                 const float* __restrict__ b_lin,
                 const float* __restrict__ W_ih,
                 const float* __restrict__ b_ih,
                 const float* __restrict__ W_hh,
                 const float* __restrict__ b_hh,
                 float* __restrict__ out,
                 int write_hlast)
{
    float* waug   = smem + OFF_W;
    float* hbuf   = smem + OFF_H;
    float* xbuf   = smem + OFF_X;
    float* stage  = smem + OFF_ST;
    float* bias_i = smem + OFF_BI;
    float* bias_h = smem + OFF_BH;

    const int tid = threadIdx.x;
    uint32_t crank;
    asm("mov.u32 %0, %%cluster_ctarank;" : "=r"(crank));
    const int c  = blockIdx.x / CL;
    const int b0 = c * NB;

    const uint32_t mb0 = smem_u32(smem + OFF_MB);
    const uint32_t mb1 = mb0 + 8;

    // ---------------- Prologue ----------------
    if (tid == 0) {
        mbar_init(mb0, 1); mbar_init(mb1, 1);
        mbar_expect_tx(mb0, TXB); mbar_expect_tx(mb1, TXB);
    }
    // W_hh rows for this CTA's 96 gate rows (k-order matches chunked h order)
    for (int f = tid; f < NROW * HH; f += THREADS) {
        int lr = f >> 8, k = f & 255;
        int g = lr >> 5, ul = lr & 31;
        int R = (g << 8) + (int)crank * NU + ul;
        waug[lr * WSTR + k] = W_hh[R * HH + k];
    }
    // W_comb = W_ih @ W_lin into waug[..][256:320]
    {
        int i = tid & 63, lr0 = tid >> 6;
        for (int jj = 0; jj < 24; jj++) {
            int lr = lr0 + 4 * jj;
            int g = lr >> 5, ul = lr & 31;
            int R = (g << 8) + (int)crank * NU + ul;
            const float4* wih = (const float4*)(W_ih + (size_t)R * HH);
            float s = 0.f;
            #pragma unroll 8
            for (int m4 = 0; m4 < HH / 4; m4++) {
                float4 w = wih[m4];
                int m = m4 << 2;
                s = fmaf(w.x, W_lin[(m + 0) * INDIM + i], s);
                s = fmaf(w.y, W_lin[(m + 1) * INDIM + i], s);
                s = fmaf(w.z, W_lin[(m + 2) * INDIM + i], s);
                s = fmaf(w.w, W_lin[(m + 3) * INDIM + i], s);
            }
            waug[lr * WSTR + HH + i] = s;
        }
    }
    // biases
    if (tid < NROW) {
        int lr = tid, g = lr >> 5, ul = lr & 31;
        int R = (g << 8) + (int)crank * NU + ul;
        float s = b_ih[R];
        for (int m = 0; m < HH; m++) s = fmaf(W_ih[R * HH + m], b_lin[m], s);
        bias_i[lr] = s;
        bias_h[lr] = b_hh[R];
    }
    // h0 into hbuf buffer 0 (chunked layout)
    for (int f = tid; f < NB * HH; f += THREADS) {
        int b = f >> 8, k = f & 255;
        int s = k >> 5, ul = k & 31;
        hbuf[s * CHUNK + b * CHSTR + ul] = hidden[(b0 + b) * HH + k];
    }
    // x(0) into xbuf buffer 0; prefetch x(1)
    float4 xpre;
    const int xbt = tid >> 4;
    const int xii = (tid & 15) << 2;
    {
        const float* xrow = inp + ((size_t)(b0 + xbt) * TT) * INDIM + xii;
        float4 v = *(const float4*)xrow;
        *(float4*)(xbuf + xbt * XSTR + xii) = v;
        xpre = *(const float4*)(xrow + INDIM);
    }
    __syncthreads();
    cluster_sync();   // peers' mbarriers armed before any sends

    // ---------------- Main recurrence ----------------
    const int u  = tid >> 3;
    const int qa = tid & 7;
    const int qb = qa + 8;
    const int jglob = (int)crank * NU + u;
    const int bga = b0 + qa, bgb = b0 + qb;

    const float bi_r = bias_i[u], bi_z = bias_i[NU + u], bi_n = bias_i[2 * NU + u];
    const float bh_r = bias_h[u], bh_z = bias_h[NU + u], bh_n = bias_h[2 * NU + u];

    const ulonglong2* wr2 = (const ulonglong2*)(waug + (0 * NU + u) * WSTR);
    const ulonglong2* wz2 = (const ulonglong2*)(waug + (1 * NU + u) * WSTR);
    const ulonglong2* wn2 = (const ulonglong2*)(waug + (2 * NU + u) * WSTR);

    const uint32_t hbuf_sm  = smem_u32(hbuf);
    const uint32_t stage_sm = smem_u32(stage);
    uint32_t mbs[2] = { mb0, mb1 };
    uint32_t ph[2]  = { 0, 0 };

    for (int t = 0; t < TT; t++) {
        const int p = t & 1;
        float* hb_p = hbuf + p * (CL * CHUNK);
        float* xb_p = xbuf + p * (NB * XSTR);

        ull ra = 0, za = 0, nha = 0, nxa = 0;
        ull rb = 0, zb = 0, nhb = 0, nxb = 0;

        // ---- x part first (local data, independent of incoming h) ----
        {
            const ulonglong2* xa2 = (const ulonglong2*)(xb_p + qa * XSTR);
            const ulonglong2* xb2 = (const ulonglong2*)(xb_p + qb * XSTR);
            #pragma unroll
            for (int kk = 0; kk < 16; kk++) {
                ulonglong2 wr = wr2[64 + kk], wz = wz2[64 + kk], wn = wn2[64 + kk];
                ulonglong2 ha = xa2[kk], hb = xb2[kk];
                ffma2(ra, wr.x, ha.x);  ffma2(ra, wr.y, ha.y);
                ffma2(za, wz.x, ha.x);  ffma2(za, wz.y, ha.y);
                ffma2(nxa, wn.x, ha.x); ffma2(nxa, wn.y, ha.y);
                ffma2(rb, wr.x, hb.x);  ffma2(rb, wr.y, hb.y);
                ffma2(zb, wz.x, hb.x);  ffma2(zb, wz.y, hb.y);
                ffma2(nxb, wn.x, hb.x); ffma2(nxb, wn.y, hb.y);
            }
        }

        // ---- wait for incoming h (hidden behind x-part) ----
        if (t > 0) {
            mbar_wait(mbs[p], ph[p]);
            ph[p] ^= 1;
            if (tid == 0) mbar_expect_tx(mbs[p], TXB);   // re-arm for t+2
        }

        // ---- h part (chunked: 8 source-CTA blocks) ----
        const float* hpa = hb_p + qa * CHSTR;
        const float* hpb = hb_p + qb * CHSTR;
        #pragma unroll 2
        for (int s = 0; s < 8; s++) {
            const ulonglong2* ha2 = (const ulonglong2*)(hpa + s * CHUNK);
            const ulonglong2* hb2 = (const ulonglong2*)(hpb + s * CHUNK);
            const int kb = s * 8;
            #pragma unroll
            for (int g = 0; g < 8; g++) {
                ulonglong2 wr = wr2[kb + g], wz = wz2[kb + g], wn = wn2[kb + g];
                ulonglong2 ha = ha2[g], hb = hb2[g];
                ffma2(ra, wr.x, ha.x);  ffma2(ra, wr.y, ha.y);
                ffma2(za, wz.x, ha.x);  ffma2(za, wz.y, ha.y);
                ffma2(nha, wn.x, ha.x); ffma2(nha, wn.y, ha.y);
                ffma2(rb, wr.x, hb.x);  ffma2(rb, wr.y, hb.y);
                ffma2(zb, wz.x, hb.x);  ffma2(zb, wz.y, hb.y);
                ffma2(nhb, wn.x, hb.x); ffma2(nhb, wn.y, hb.y);
            }
        }

        // gates
        float hold_a = hb_p[crank * CHUNK + qa * CHSTR + u];
        float hold_b = hb_p[crank * CHUNK + qb * CHSTR + u];
        float rg_a = sigm(hsum2(ra) + bi_r + bh_r);
        float zg_a = sigm(hsum2(za) + bi_z + bh_z);
        float ng_a = tanh_fast(hsum2(nxa) + bi_n + rg_a * (hsum2(nha) + bh_n));
        float hn_a = (1.f - zg_a) * ng_a + zg_a * hold_a;
        float rg_b = sigm(hsum2(rb) + bi_r + bh_r);
        float zg_b = sigm(hsum2(zb) + bi_z + bh_z);
        float ng_b = tanh_fast(hsum2(nxb) + bi_n + rg_b * (hsum2(nhb) + bh_n));
        float hn_b = (1.f - zg_b) * ng_b + zg_b * hold_b;

        // outputs
        out[((size_t)bga * TT + t) * HH + jglob] = hn_a;
        out[((size_t)bgb * TT + t) * HH + jglob] = hn_b;
        if (write_hlast && t == TT - 1) {
            out[(size_t)BATCH * TT * HH + (size_t)bga * HH + jglob] = hn_a;
            out[(size_t)BATCH * TT * HH + (size_t)bgb * HH + jglob] = hn_b;
        }

        if (t < TT - 1) {
            // stage h_new locally (conflict-free: bank 4q+u)
            float* st_p = stage + p * (NB * CHSTR);
            st_p[qa * CHSTR + u] = hn_a;
            st_p[qb * CHSTR + u] = hn_b;

            // stage x(t+1) into next buffer
            *(float4*)(xbuf + (1 - p) * (NB * XSTR) + xbt * XSTR + xii) = xpre;
            if (t < TT - 2)
                xpre = *(const float4*)(inp + ((size_t)(b0 + xbt) * TT + (t + 2)) * INDIM + xii);

            __syncthreads();   // staging complete before bulk copies

            // 8 bulk copies: our 2304B block -> each peer's hbuf[1-p] chunk slot
            if (tid < CL) {
                fence_async_shared();
                uint32_t src = stage_sm + (uint32_t)(p * (NB * CHSTR) * 4);
                uint32_t dst = hbuf_sm + (uint32_t)(((1 - p) * (CL * CHUNK) + (int)crank * CHUNK) * 4);
                dsmem_bulk_cp(dst, src, mbs[1 - p], (uint32_t)tid, (uint32_t)(CHUNK * 4));
            }
        }
    }
    cluster_sync();   // no CTA exits while peers may still reference cluster smem

    (void)mb1;
}

extern "C" void kernel_launch(void* const* d_in, const int* in_sizes, int n_in,
                              void* d_out, int out_size) {
    (void)in_sizes; (void)n_in;
    const float* inp    = (const float*)d_in[0];
    const float* hidden = (const float*)d_in[1];
    const float* W_lin  = (const float*)d_in[2];
    const float* b_lin  = (const float*)d_in[3];
    const float* W_ih   = (const float*)d_in[4];
    const float* b_ih   = (const float*)d_in[5];
    const float* W_hh   = (const float*)d_in[6];
    const float* b_hh   = (const float*)d_in[7];

    const int smem_bytes = SMEM_FL * (int)sizeof(float);
    cudaFuncSetAttribute(gru_fused_kernel,
                         cudaFuncAttributeMaxDynamicSharedMemorySize, smem_bytes);

    const int write_hlast = (out_size > BATCH * TT * HH) ? 1 : 0;
    const int grid = (BATCH / NB) * CL;   // 128
    gru_fused_kernel<<<grid, THREADS, smem_bytes>>>(
        inp, hidden, W_lin, b_lin, W_ih, b_ih, W_hh, b_hh,
        (float*)d_out, write_hlast);
}